// round 4
// baseline (speedup 1.0000x reference)
#include <cuda_runtime.h>

#define N_MAX 100000
#define E_MAX 1600000

// ---------------- scratch (static device arrays; no allocation) ----------------
__device__ float g_h  [(size_t)N_MAX * 96];   // per-layer node features h = x @ W
__device__ float g_out[(size_t)N_MAX * 96];   // GAT aggregation output
__device__ float g_y  [(size_t)N_MAX * 32];   // reshape(3,N,32).sum(0) result
__device__ float g_s  [N_MAX];                // h @ a_src
__device__ float g_d  [N_MAX];                // h @ a_dst
__device__ int   g_rowptr[N_MAX + 1];
__device__ int   g_cnt[N_MAX];
__device__ int   g_col[E_MAX];

// ---------------- CSR build ----------------
__global__ void k_zero_cnt(int Nn) {
    int i = blockIdx.x * blockDim.x + threadIdx.x;
    if (i < Nn) g_cnt[i] = 0;
}

__global__ void k_hist(const int* __restrict__ ei, int E, int Nn) {
    for (int e = blockIdx.x * blockDim.x + threadIdx.x; e < E; e += gridDim.x * blockDim.x) {
        int dd = ei[E + e];
        if ((unsigned)dd < (unsigned)Nn) atomicAdd(&g_cnt[dd], 1);
    }
}

__global__ void k_scan(int Nn) {
    __shared__ int sm[1024];
    int t = threadIdx.x;
    int C = (Nn + 1023) >> 10;
    int b = t * C;
    int e = b + C; if (e > Nn) e = Nn;
    if (b > Nn) b = Nn;
    int sum = 0;
    for (int i = b; i < e; i++) sum += g_cnt[i];
    sm[t] = sum;
    __syncthreads();
    for (int off = 1; off < 1024; off <<= 1) {
        int v = (t >= off) ? sm[t - off] : 0;
        __syncthreads();
        sm[t] += v;
        __syncthreads();
    }
    int run = sm[t] - sum;  // exclusive prefix
    for (int i = b; i < e; i++) { g_rowptr[i] = run; run += g_cnt[i]; }
    if (t == 1023) g_rowptr[Nn] = sm[1023];
}

__global__ void k_scatter(const int* __restrict__ ei, int E, int Nn) {
    for (int e = blockIdx.x * blockDim.x + threadIdx.x; e < E; e += gridDim.x * blockDim.x) {
        int ss = ei[e];
        int dd = ei[E + e];
        if ((unsigned)dd < (unsigned)Nn) {
            int pos = g_rowptr[dd] + atomicAdd(&g_cnt[dd], 1);
            g_col[pos] = ss;
        }
    }
}

// ---------------- register-tiled GEMM: C[M,BN] = A[M,K] @ B[K,BN] (+bias, act) ----------------
// ACT: 0 = none, 1 = relu, 2 = sigmoid
template <int BN, int TN, int ACT>
__global__ void __launch_bounds__(256) k_gemm(const float* __restrict__ A,
                                              const float* __restrict__ B,
                                              const float* __restrict__ bias,
                                              float* __restrict__ C,
                                              int M, int K) {
    constexpr int BM = 128, BK = 32, TM = 8;
    constexpr int TX = BN / TN;          // 16
    __shared__ float As[BM][BK + 1];
    __shared__ float Bs[BK][BN + 1];
    int tid = threadIdx.x;
    int tx = tid % TX, ty = tid / TX;
    int row0 = blockIdx.x * BM;

    float acc[TM][TN];
#pragma unroll
    for (int r = 0; r < TM; r++)
#pragma unroll
        for (int c = 0; c < TN; c++) acc[r][c] = 0.f;

    for (int k0 = 0; k0 < K; k0 += BK) {
        // load A tile (BM x BK) as float4
        for (int i = tid; i < BM * (BK / 4); i += 256) {
            int r = i >> 3;           // / (BK/4)
            int c4 = i & 7;
            int gr = row0 + r;
            float4 v = make_float4(0.f, 0.f, 0.f, 0.f);
            if (gr < M) v = *(const float4*)&A[(size_t)gr * K + k0 + (c4 << 2)];
            As[r][(c4 << 2) + 0] = v.x;
            As[r][(c4 << 2) + 1] = v.y;
            As[r][(c4 << 2) + 2] = v.z;
            As[r][(c4 << 2) + 3] = v.w;
        }
        // load B tile (BK x BN) as float4
        for (int i = tid; i < BK * (BN / 4); i += 256) {
            int r = i / (BN / 4);
            int c4 = i % (BN / 4);
            float4 v = *(const float4*)&B[(size_t)(k0 + r) * BN + (c4 << 2)];
            Bs[r][(c4 << 2) + 0] = v.x;
            Bs[r][(c4 << 2) + 1] = v.y;
            Bs[r][(c4 << 2) + 2] = v.z;
            Bs[r][(c4 << 2) + 3] = v.w;
        }
        __syncthreads();
#pragma unroll
        for (int kk = 0; kk < BK; kk++) {
            float a[TM], bb[TN];
#pragma unroll
            for (int r = 0; r < TM; r++) a[r] = As[ty * TM + r][kk];
#pragma unroll
            for (int c = 0; c < TN; c++) bb[c] = Bs[kk][tx * TN + c];
#pragma unroll
            for (int r = 0; r < TM; r++)
#pragma unroll
                for (int c = 0; c < TN; c++) acc[r][c] += a[r] * bb[c];
        }
        __syncthreads();
    }

#pragma unroll
    for (int r = 0; r < TM; r++) {
        int gr = row0 + ty * TM + r;
        if (gr < M) {
#pragma unroll
            for (int c = 0; c < TN; c++) {
                int col = tx * TN + c;
                float v = acc[r][c];
                if (bias) v += bias[col];
                if (ACT == 1) v = fmaxf(v, 0.f);
                if (ACT == 2) v = 1.f / (1.f + __expf(-v));
                C[(size_t)gr * BN + col] = v;
            }
        }
    }
}

// ---------------- s = h @ a_src, d = h @ a_dst (warp per node) ----------------
__global__ void k_sd(const float* __restrict__ h, const float* __restrict__ as_,
                     const float* __restrict__ ad_, int Nn) {
    int w = (int)((blockIdx.x * blockDim.x + threadIdx.x) >> 5);
    int lane = threadIdx.x & 31;
    if (w >= Nn) return;
    const float* hr = h + (size_t)w * 96;
    float s = 0.f, d = 0.f;
#pragma unroll
    for (int u = 0; u < 3; u++) {
        float hv = hr[lane + 32 * u];
        s += hv * as_[lane + 32 * u];
        d += hv * ad_[lane + 32 * u];
    }
#pragma unroll
    for (int off = 16; off; off >>= 1) {
        s += __shfl_xor_sync(0xffffffffu, s, off);
        d += __shfl_xor_sync(0xffffffffu, d, off);
    }
    if (lane == 0) { g_s[w] = s; g_d[w] = d; }
}

// ---------------- GAT softmax-aggregate (warp per dst node) ----------------
__device__ __forceinline__ float lrelu(float x) { return x > 0.f ? x : 0.2f * x; }

__global__ void k_agg(const float* __restrict__ h, const float* __restrict__ bias,
                      float* __restrict__ out, int Nn) {
    int n = (int)((blockIdx.x * blockDim.x + threadIdx.x) >> 5);
    int lane = threadIdx.x & 31;
    if (n >= Nn) return;
    int beg = g_rowptr[n];
    int end = g_rowptr[n + 1];
    float dn = g_d[n];

    // pass 1: online softmax max+sum (lane-parallel over edges; self-loop on lane 0)
    float m, p;
    if (lane == 0) {
        m = lrelu(g_s[n] + dn);
        p = 1.0f;
    } else {
        m = -1e30f;
        p = 0.f;
    }
    for (int j = beg + lane; j < end; j += 32) {
        float e = lrelu(g_s[g_col[j]] + dn);
        if (e > m) { p = p * __expf(m - e) + 1.0f; m = e; }
        else        p += __expf(e - m);
    }
#pragma unroll
    for (int off = 16; off; off >>= 1) {
        float mo = __shfl_xor_sync(0xffffffffu, m, off);
        float po = __shfl_xor_sync(0xffffffffu, p, off);
        float mn = fmaxf(m, mo);
        float pn = (p  > 0.f ? p  * __expf(m  - mn) : 0.f) +
                   (po > 0.f ? po * __expf(mo - mn) : 0.f);
        m = mn; p = pn;
    }

    // pass 2: weighted aggregation (whole warp per edge; 96 cols = 3 per lane)
    float a0, a1, a2;
    {
        float w0 = __expf(lrelu(g_s[n] + dn) - m);   // self-loop
        const float* hr = h + (size_t)n * 96;
        a0 = w0 * hr[lane];
        a1 = w0 * hr[lane + 32];
        a2 = w0 * hr[lane + 64];
    }
    for (int j = beg; j < end; j++) {
        int c = g_col[j];
        float w0 = __expf(lrelu(g_s[c] + dn) - m);
        const float* hr = h + (size_t)c * 96;
        a0 += w0 * hr[lane];
        a1 += w0 * hr[lane + 32];
        a2 += w0 * hr[lane + 64];
    }
    float scale = 1.f / (fmaxf(p, 1e-16f) * (float)(end - beg + 1));
    float* o = out + (size_t)n * 96;
    o[lane]      = a0 * scale + bias[lane];
    o[lane + 32] = a1 * scale + bias[lane + 32];
    o[lane + 64] = a2 * scale + bias[lane + 64];
}

// ---------------- faithful view(3,N,32).sum(0) [+relu] ----------------
__global__ void k_reshape(const float* __restrict__ src, float* __restrict__ dst,
                          int Nn, int doRelu) {
    int t = blockIdx.x * blockDim.x + threadIdx.x;
    int tot = Nn * 32;
    if (t >= tot) return;
    float v = src[t] + src[t + tot] + src[t + 2 * tot];
    if (doRelu) v = fmaxf(v, 0.f);
    dst[t] = v;
}

// ---------------- launch ----------------
extern "C" void kernel_launch(void* const* d_in, const int* in_sizes, int n_in,
                              void* d_out, int out_size) {
    const float* x   = (const float*)d_in[0];
    const int*   ei  = (const int*)d_in[1];          // int64 in ref -> int32 in harness
    const float* W1  = (const float*)d_in[2];
    const float* as1 = (const float*)d_in[3];
    const float* ad1 = (const float*)d_in[4];
    const float* b1  = (const float*)d_in[5];
    const float* W2  = (const float*)d_in[6];
    const float* as2 = (const float*)d_in[7];
    const float* ad2 = (const float*)d_in[8];
    const float* b2  = (const float*)d_in[9];
    const float* Wl1 = (const float*)d_in[12];
    const float* bl1 = (const float*)d_in[13];
    const float* Wl2 = (const float*)d_in[14];
    const float* bl2 = (const float*)d_in[15];
    float* out = (float*)d_out;

    int Nn = in_sizes[0] / 128;
    int E  = in_sizes[1] / 2;
    if (Nn > N_MAX) Nn = N_MAX;
    if (E  > E_MAX) E  = E_MAX;

    float *p_h, *p_out, *p_y;
    cudaGetSymbolAddress((void**)&p_h,   g_h);
    cudaGetSymbolAddress((void**)&p_out, g_out);
    cudaGetSymbolAddress((void**)&p_y,   g_y);

    // ---- CSR build (per call; deterministic work) ----
    k_zero_cnt<<<(Nn + 255) / 256, 256>>>(Nn);
    k_hist<<<1024, 256>>>(ei, E, Nn);
    k_scan<<<1, 1024>>>(Nn);
    k_zero_cnt<<<(Nn + 255) / 256, 256>>>(Nn);
    k_scatter<<<1024, 256>>>(ei, E, Nn);

    int gb = (Nn + 127) / 128;
    int wb = (Nn + 7) / 8;            // warp-per-node kernels, 8 warps/block
    int rb = (Nn * 32 + 255) / 256;

    // ---- layer 1 ----
    k_gemm<96, 6, 0><<<gb, 256>>>(x, W1, nullptr, p_h, Nn, 128);
    k_sd<<<wb, 256>>>(p_h, as1, ad1, Nn);
    k_agg<<<wb, 256>>>(p_h, b1, p_out, Nn);
    k_reshape<<<rb, 256>>>(p_out, p_y, Nn, 1);

    // ---- layer 2 ----
    k_gemm<96, 6, 0><<<gb, 256>>>(p_y, W2, nullptr, p_h, Nn, 32);
    k_sd<<<wb, 256>>>(p_h, as2, ad2, Nn);
    k_agg<<<wb, 256>>>(p_h, b2, p_out, Nn);
    k_reshape<<<rb, 256>>>(p_out, p_y, Nn, 0);

    // ---- MLP head ----
    k_gemm<96, 6, 1><<<gb, 256>>>(p_y, Wl1, bl1, p_h, Nn, 32);
    k_gemm<32, 2, 2><<<gb, 256>>>(p_h, Wl2, bl2, out, Nn, 96);

    (void)n_in; (void)out_size;
}

// round 5
// speedup vs baseline: 1.0392x; 1.0392x over previous
#include <cuda_runtime.h>

#define N_MAX 100000
#define E_MAX 1600000

// ---------------- scratch (static device arrays; no allocation) ----------------
__device__ float g_h  [(size_t)N_MAX * 96];   // per-layer node features h = x @ W
__device__ float g_out[(size_t)N_MAX * 96];   // GAT aggregation output
__device__ float g_y  [(size_t)N_MAX * 32];   // reshape(3,N,32).sum(0) result
__device__ float g_s  [N_MAX];                // h @ a_src
__device__ float g_d  [N_MAX];                // h @ a_dst
__device__ int   g_rowptr[N_MAX + 1];
__device__ int   g_cnt[N_MAX];
__device__ int   g_col[E_MAX];

// ---------------- CSR build ----------------
__global__ void k_zero_cnt(int Nn) {
    int i = blockIdx.x * blockDim.x + threadIdx.x;
    if (i < Nn) g_cnt[i] = 0;
}

__global__ void k_hist(const int* __restrict__ ei, int E, int Nn) {
    for (int e = blockIdx.x * blockDim.x + threadIdx.x; e < E; e += gridDim.x * blockDim.x) {
        int dd = ei[E + e];
        if ((unsigned)dd < (unsigned)Nn) atomicAdd(&g_cnt[dd], 1);
    }
}

__global__ void k_scan(int Nn) {
    __shared__ int sm[1024];
    int t = threadIdx.x;
    int C = (Nn + 1023) >> 10;
    int b = t * C;
    int e = b + C; if (e > Nn) e = Nn;
    if (b > Nn) b = Nn;
    int sum = 0;
    for (int i = b; i < e; i++) sum += g_cnt[i];
    sm[t] = sum;
    __syncthreads();
    for (int off = 1; off < 1024; off <<= 1) {
        int v = (t >= off) ? sm[t - off] : 0;
        __syncthreads();
        sm[t] += v;
        __syncthreads();
    }
    int run = sm[t] - sum;  // exclusive prefix
    for (int i = b; i < e; i++) { g_rowptr[i] = run; run += g_cnt[i]; }
    if (t == 1023) g_rowptr[Nn] = sm[1023];
}

__global__ void k_scatter(const int* __restrict__ ei, int E, int Nn) {
    for (int e = blockIdx.x * blockDim.x + threadIdx.x; e < E; e += gridDim.x * blockDim.x) {
        int ss = ei[e];
        int dd = ei[E + e];
        if ((unsigned)dd < (unsigned)Nn) {
            int pos = g_rowptr[dd] + atomicAdd(&g_cnt[dd], 1);
            g_col[pos] = ss;
        }
    }
}

// ---------------- register-tiled GEMM: C[M,BN] = A[M,K] @ B[K,BN] (+bias, act) ----------------
// ACT: 0 = none, 1 = relu, 2 = sigmoid
template <int BN, int TN, int ACT>
__global__ void __launch_bounds__(256) k_gemm(const float* __restrict__ A,
                                              const float* __restrict__ B,
                                              const float* __restrict__ bias,
                                              float* __restrict__ C,
                                              int M, int K) {
    constexpr int BM = 128, BK = 32, TM = 8;
    constexpr int TX = BN / TN;          // 16
    __shared__ float As[BM][BK + 1];
    __shared__ float Bs[BK][BN + 1];
    int tid = threadIdx.x;
    int tx = tid % TX, ty = tid / TX;
    int row0 = blockIdx.x * BM;

    float acc[TM][TN];
#pragma unroll
    for (int r = 0; r < TM; r++)
#pragma unroll
        for (int c = 0; c < TN; c++) acc[r][c] = 0.f;

    for (int k0 = 0; k0 < K; k0 += BK) {
        // load A tile (BM x BK) as float4
        for (int i = tid; i < BM * (BK / 4); i += 256) {
            int r = i >> 3;           // / (BK/4)
            int c4 = i & 7;
            int gr = row0 + r;
            float4 v = make_float4(0.f, 0.f, 0.f, 0.f);
            if (gr < M) v = *(const float4*)&A[(size_t)gr * K + k0 + (c4 << 2)];
            As[r][(c4 << 2) + 0] = v.x;
            As[r][(c4 << 2) + 1] = v.y;
            As[r][(c4 << 2) + 2] = v.z;
            As[r][(c4 << 2) + 3] = v.w;
        }
        // load B tile (BK x BN) as float4
        for (int i = tid; i < BK * (BN / 4); i += 256) {
            int r = i / (BN / 4);
            int c4 = i % (BN / 4);
            float4 v = *(const float4*)&B[(size_t)(k0 + r) * BN + (c4 << 2)];
            Bs[r][(c4 << 2) + 0] = v.x;
            Bs[r][(c4 << 2) + 1] = v.y;
            Bs[r][(c4 << 2) + 2] = v.z;
            Bs[r][(c4 << 2) + 3] = v.w;
        }
        __syncthreads();
#pragma unroll
        for (int kk = 0; kk < BK; kk++) {
            float a[TM], bb[TN];
#pragma unroll
            for (int r = 0; r < TM; r++) a[r] = As[ty * TM + r][kk];
#pragma unroll
            for (int c = 0; c < TN; c++) bb[c] = Bs[kk][tx * TN + c];
#pragma unroll
            for (int r = 0; r < TM; r++)
#pragma unroll
                for (int c = 0; c < TN; c++) acc[r][c] += a[r] * bb[c];
        }
        __syncthreads();
    }

#pragma unroll
    for (int r = 0; r < TM; r++) {
        int gr = row0 + ty * TM + r;
        if (gr < M) {
#pragma unroll
            for (int c = 0; c < TN; c++) {
                int col = tx * TN + c;
                float v = acc[r][c];
                if (bias) v += bias[col];
                if (ACT == 1) v = fmaxf(v, 0.f);
                if (ACT == 2) v = 1.f / (1.f + __expf(-v));
                C[(size_t)gr * BN + col] = v;
            }
        }
    }
}

// ---------------- s = h @ a_src, d = h @ a_dst (warp per node) ----------------
__global__ void k_sd(const float* __restrict__ h, const float* __restrict__ as_,
                     const float* __restrict__ ad_, int Nn) {
    int w = (int)((blockIdx.x * blockDim.x + threadIdx.x) >> 5);
    int lane = threadIdx.x & 31;
    if (w >= Nn) return;
    const float* hr = h + (size_t)w * 96;
    float s = 0.f, d = 0.f;
#pragma unroll
    for (int u = 0; u < 3; u++) {
        float hv = hr[lane + 32 * u];
        s += hv * as_[lane + 32 * u];
        d += hv * ad_[lane + 32 * u];
    }
#pragma unroll
    for (int off = 16; off; off >>= 1) {
        s += __shfl_xor_sync(0xffffffffu, s, off);
        d += __shfl_xor_sync(0xffffffffu, d, off);
    }
    if (lane == 0) { g_s[w] = s; g_d[w] = d; }
}

// ---------------- GAT softmax-aggregate (warp per dst node) ----------------
__device__ __forceinline__ float lrelu(float x) { return x > 0.f ? x : 0.2f * x; }

__global__ void k_agg(const float* __restrict__ h, const float* __restrict__ bias,
                      float* __restrict__ out, int Nn) {
    int n = (int)((blockIdx.x * blockDim.x + threadIdx.x) >> 5);
    int lane = threadIdx.x & 31;
    if (n >= Nn) return;
    int beg = g_rowptr[n];
    int end = g_rowptr[n + 1];
    float dn = g_d[n];
    float e_self = lrelu(g_s[n] + dn);

    // ---- pass 1: pure max over edge scores (no exp) ----
    float m = e_self;
    for (int j = beg + lane; j < end; j += 32)
        m = fmaxf(m, lrelu(g_s[g_col[j]] + dn));
#pragma unroll
    for (int off = 16; off; off >>= 1)
        m = fmaxf(m, __shfl_xor_sync(0xffffffffu, m, off));

    // ---- pass 2: chunked exp (1 MUFU per edge) + broadcast accumulate ----
    float w_self = __expf(e_self - m);
    float p = (lane == 0) ? w_self : 0.f;   // softmax denominator, lane-partial
    float a0, a1, a2;
    {
        const float* hr = h + (size_t)n * 96;
        a0 = w_self * hr[lane];
        a1 = w_self * hr[lane + 32];
        a2 = w_self * hr[lane + 64];
    }
    for (int j0 = beg; j0 < end; j0 += 32) {
        int j = j0 + lane;
        int c = 0;
        float w = 0.f;
        if (j < end) {
            c = g_col[j];
            w = __expf(lrelu(g_s[c] + dn) - m);
            p += w;
        }
        int cnt = end - j0; if (cnt > 32) cnt = 32;
        for (int t = 0; t < cnt; t++) {
            float wt = __shfl_sync(0xffffffffu, w, t);
            int   ct = __shfl_sync(0xffffffffu, c, t);
            const float* hr = h + (size_t)ct * 96;
            a0 += wt * hr[lane];
            a1 += wt * hr[lane + 32];
            a2 += wt * hr[lane + 64];
        }
    }
#pragma unroll
    for (int off = 16; off; off >>= 1)
        p += __shfl_xor_sync(0xffffffffu, p, off);

    float scale = 1.f / (fmaxf(p, 1e-16f) * (float)(end - beg + 1));
    float* o = out + (size_t)n * 96;
    o[lane]      = a0 * scale + bias[lane];
    o[lane + 32] = a1 * scale + bias[lane + 32];
    o[lane + 64] = a2 * scale + bias[lane + 64];
}

// ---------------- faithful view(3,N,32).sum(0) [+relu] ----------------
__global__ void k_reshape(const float* __restrict__ src, float* __restrict__ dst,
                          int Nn, int doRelu) {
    int t = blockIdx.x * blockDim.x + threadIdx.x;
    int tot = Nn * 32;
    if (t >= tot) return;
    float v = src[t] + src[t + tot] + src[t + 2 * tot];
    if (doRelu) v = fmaxf(v, 0.f);
    dst[t] = v;
}

// ---------------- launch ----------------
extern "C" void kernel_launch(void* const* d_in, const int* in_sizes, int n_in,
                              void* d_out, int out_size) {
    const float* x   = (const float*)d_in[0];
    const int*   ei  = (const int*)d_in[1];          // int64 in ref -> int32 in harness
    const float* W1  = (const float*)d_in[2];
    const float* as1 = (const float*)d_in[3];
    const float* ad1 = (const float*)d_in[4];
    const float* b1  = (const float*)d_in[5];
    const float* W2  = (const float*)d_in[6];
    const float* as2 = (const float*)d_in[7];
    const float* ad2 = (const float*)d_in[8];
    const float* b2  = (const float*)d_in[9];
    const float* Wl1 = (const float*)d_in[12];
    const float* bl1 = (const float*)d_in[13];
    const float* Wl2 = (const float*)d_in[14];
    const float* bl2 = (const float*)d_in[15];
    float* out = (float*)d_out;

    int Nn = in_sizes[0] / 128;
    int E  = in_sizes[1] / 2;
    if (Nn > N_MAX) Nn = N_MAX;
    if (E  > E_MAX) E  = E_MAX;

    float *p_h, *p_out, *p_y;
    cudaGetSymbolAddress((void**)&p_h,   g_h);
    cudaGetSymbolAddress((void**)&p_out, g_out);
    cudaGetSymbolAddress((void**)&p_y,   g_y);

    // ---- CSR build (per call; deterministic work) ----
    k_zero_cnt<<<(Nn + 255) / 256, 256>>>(Nn);
    k_hist<<<1024, 256>>>(ei, E, Nn);
    k_scan<<<1, 1024>>>(Nn);
    k_zero_cnt<<<(Nn + 255) / 256, 256>>>(Nn);
    k_scatter<<<1024, 256>>>(ei, E, Nn);

    int gb = (Nn + 127) / 128;
    int wb = (Nn + 7) / 8;            // warp-per-node kernels, 8 warps/block
    int rb = (Nn * 32 + 255) / 256;

    // ---- layer 1 ----
    k_gemm<96, 6, 0><<<gb, 256>>>(x, W1, nullptr, p_h, Nn, 128);
    k_sd<<<wb, 256>>>(p_h, as1, ad1, Nn);
    k_agg<<<wb, 256>>>(p_h, b1, p_out, Nn);
    k_reshape<<<rb, 256>>>(p_out, p_y, Nn, 1);

    // ---- layer 2 ----
    k_gemm<96, 6, 0><<<gb, 256>>>(p_y, W2, nullptr, p_h, Nn, 32);
    k_sd<<<wb, 256>>>(p_h, as2, ad2, Nn);
    k_agg<<<wb, 256>>>(p_h, b2, p_out, Nn);
    k_reshape<<<rb, 256>>>(p_out, p_y, Nn, 0);

    // ---- MLP head ----
    k_gemm<96, 6, 1><<<gb, 256>>>(p_y, Wl1, bl1, p_h, Nn, 32);
    k_gemm<32, 2, 2><<<gb, 256>>>(p_h, Wl2, bl2, out, Nn, 96);

    (void)n_in; (void)out_size;
}